// round 1
// baseline (speedup 1.0000x reference)
#include <cuda_runtime.h>
#include <math.h>

#define DEV_INLINE __device__ __forceinline__

// Problem constants
constexpr int B_  = 2;
constexpr int N_  = 2048;
constexpr int D_  = 512;
constexpr int H_  = 8;
constexpr int DH_ = 64;
constexpr int MROWS = B_ * N_;            // 4096
constexpr long NN   = (long)N_ * N_;      // 4194304 per (b,h) sim slice
constexpr long NDL  = (long)N_ * D_;      // 1048576 per-batch stride for [b,n,512]
constexpr int  BHN  = B_ * H_ * N_;       // 32768 rows of sim

// ---------------- scratch (static device globals; no runtime allocation) ----
__device__ float g_xn  [B_*N_*D_];
__device__ float g_cn  [B_*N_*D_];
__device__ float g_qk  [B_*N_*D_];
__device__ float g_cqk [B_*N_*D_];
__device__ float g_v   [B_*N_*D_];
__device__ float g_cv  [B_*N_*D_];
__device__ float g_vt  [B_*N_*D_];        // v scaled by exp(rowmax_i)
__device__ float g_sim [67108864];        // [b,h,i,j] logits -> E in place (268MB)
__device__ float g_rsum[B_*H_*N_];        // row sums of E
__device__ float g_texp[B_*H_*N_];        // exp(rowmax_i)
__device__ float g_csum[B_*H_*N_];        // col sums of exp(sim)
__device__ float g_outh[B_*N_*D_];        // merged-head attn output (x side)
__device__ float g_ctxh[B_*N_*D_];        // merged-head attn output (context side)

// ---------------- fast exp on the FMA pipe (avoids MUFU bottleneck) ---------
DEV_INLINE float fexp(float x) {
    x = fmaxf(x, -80.0f);                       // keep result normal
    float t = x * 1.4426950408889634f;          // log2(e)
    float z = t + 12582912.0f;                  // round-to-nearest magic
    float fi = z - 12582912.0f;
    float f  = t - fi;                          // f in [-0.5, 0.5]
    int   i  = __float_as_int(z) - 0x4B400000;  // integer part
    float p = 1.3333558146428443e-3f;           // 2^f Taylor (deg 5)
    p = fmaf(p, f, 9.618129107628477e-3f);
    p = fmaf(p, f, 5.550410866482158e-2f);
    p = fmaf(p, f, 2.402265069591007e-1f);
    p = fmaf(p, f, 6.931471805599453e-1f);
    p = fmaf(p, f, 1.0f);
    return __int_as_float(__float_as_int(p) + (i << 23));
}

// ---------------- reductions ------------------------------------------------
DEV_INLINE float warpReduceSum(float v) {
    #pragma unroll
    for (int o = 16; o > 0; o >>= 1) v += __shfl_xor_sync(0xffffffffu, v, o);
    return v;
}
DEV_INLINE float warpReduceMax(float v) {
    #pragma unroll
    for (int o = 16; o > 0; o >>= 1) v = fmaxf(v, __shfl_xor_sync(0xffffffffu, v, o));
    return v;
}
template<int NT>
DEV_INLINE float blockReduceSum(float v, float* sh) {
    v = warpReduceSum(v);
    int lane = threadIdx.x & 31, w = threadIdx.x >> 5;
    if (lane == 0) sh[w] = v;
    __syncthreads();
    if (w == 0) {
        float x = (lane < NT/32) ? sh[lane] : 0.0f;
        x = warpReduceSum(x);
        if (lane == 0) sh[0] = x;
    }
    __syncthreads();
    float r = sh[0];
    __syncthreads();
    return r;
}
template<int NT>
DEV_INLINE float blockReduceMax(float v, float* sh) {
    v = warpReduceMax(v);
    int lane = threadIdx.x & 31, w = threadIdx.x >> 5;
    if (lane == 0) sh[w] = v;
    __syncthreads();
    if (w == 0) {
        float x = (lane < NT/32) ? sh[lane] : -3.4e38f;
        x = warpReduceMax(x);
        if (lane == 0) sh[0] = x;
    }
    __syncthreads();
    float r = sh[0];
    __syncthreads();
    return r;
}

// ---------------- layernorm: one block (128 thr) per 512-wide row -----------
__global__ void ln_kernel(const float* __restrict__ x,
                          const float* __restrict__ g,
                          const float* __restrict__ b,
                          float* __restrict__ y) {
    __shared__ float sh[32];
    long row = blockIdx.x;
    const float4* xr = (const float4*)(x + row * D_);
    float4 v = xr[threadIdx.x];
    float s  = v.x + v.y + v.z + v.w;
    float sq = v.x*v.x + v.y*v.y + v.z*v.z + v.w*v.w;
    s  = blockReduceSum<128>(s,  sh);
    sq = blockReduceSum<128>(sq, sh);
    float mu   = s * (1.0f / D_);
    float var  = sq * (1.0f / D_) - mu * mu;
    float rstd = rsqrtf(var + 1e-5f);
    float4 gg = ((const float4*)g)[threadIdx.x];
    float4 bb = ((const float4*)b)[threadIdx.x];
    float4 o;
    o.x = (v.x - mu) * rstd * gg.x + bb.x;
    o.y = (v.y - mu) * rstd * gg.y + bb.y;
    o.z = (v.z - mu) * rstd * gg.z + bb.z;
    o.w = (v.w - mu) * rstd * gg.w + bb.w;
    ((float4*)(y + row * D_))[threadIdx.x] = o;
}

// ---------------- row softmax pass: sim -> E, store rsum & exp(rowmax) ------
__global__ void row_softmax_kernel(float* __restrict__ sim,
                                   float* __restrict__ rsum,
                                   float* __restrict__ texp) {
    __shared__ float sh[32];
    long row = blockIdx.x;                       // 0..32767
    float4* p = (float4*)(sim + row * N_);
    int t = threadIdx.x;                         // 256 threads, 8 floats each
    float4 a = p[t];
    float4 c = p[t + 256];
    float m = fmaxf(fmaxf(fmaxf(a.x, a.y), fmaxf(a.z, a.w)),
                    fmaxf(fmaxf(c.x, c.y), fmaxf(c.z, c.w)));
    m = blockReduceMax<256>(m, sh);
    a.x = fexp(a.x - m); a.y = fexp(a.y - m); a.z = fexp(a.z - m); a.w = fexp(a.w - m);
    c.x = fexp(c.x - m); c.y = fexp(c.y - m); c.z = fexp(c.z - m); c.w = fexp(c.w - m);
    float s = a.x + a.y + a.z + a.w + c.x + c.y + c.z + c.w;
    s = blockReduceSum<256>(s, sh);
    p[t] = a;
    p[t + 256] = c;
    if (t == 0) { rsum[row] = s; texp[row] = fexp(m); }
}

// ---------------- column sums: csum_j = sum_i E[i,j] * exp(rowmax_i) --------
__global__ void zero_kernel(float* __restrict__ p, int n) {
    int i = blockIdx.x * blockDim.x + threadIdx.x;
    if (i < n) p[i] = 0.0f;
}
__global__ void colsum_kernel(const float* __restrict__ sim,
                              const float* __restrict__ texp,
                              float* __restrict__ csum) {
    int z  = blockIdx.z;
    int j  = blockIdx.x * blockDim.x + threadIdx.x;
    int i0 = blockIdx.y * 256;
    const float* E  = sim + (long)z * NN;
    const float* tz = texp + z * N_;
    float s = 0.0f;
    #pragma unroll 8
    for (int i = i0; i < i0 + 256; ++i)
        s += E[(long)i * N_ + j] * tz[i];
    atomicAdd(&csum[z * N_ + j], s);
}

// ---------------- vt[b,i,h*64+d] = v * exp(rowmax_{b,h,i}) ------------------
__global__ void scale_v_kernel(const float4* __restrict__ v,
                               const float* __restrict__ texp,
                               float4* __restrict__ vt) {
    int e = blockIdx.x * blockDim.x + threadIdx.x;   // float4 index, 524288 total
    constexpr int PER_B = N_ * D_ / 4;
    int b  = e / PER_B;
    int r  = e - b * PER_B;
    int i  = r / (D_ / 4);
    int c4 = r - i * (D_ / 4);
    int h  = (c4 * 4) >> 6;
    float tv = texp[(b * H_ + h) * N_ + i];
    float4 x = v[e];
    x.x *= tv; x.y *= tv; x.z *= tv; x.w *= tv;
    vt[e] = x;
}

// ---------------- generic fp32 tiled GEMM -----------------------------------
// C[M,N] = op(A) * op(B); TA: A stored [K,M]; TB: B stored [N,K].
// EPI 0: C = alpha*acc   EPI 2: C = acc + bias[col]   EPI 3: C = acc / rs[row]
template<int BM,int BN,int BK,int TM,int TN,bool TA,bool TB,int EPI>
__global__ void __launch_bounds__((BM/TM)*(BN/TN))
gemm_k(const float* __restrict__ A, int lda, long sAb, long sAh,
       const float* __restrict__ Bp, int ldb, long sBb, long sBh,
       float* __restrict__ C, int ldc, long sCb, long sCh,
       int K, float alpha,
       const float* __restrict__ rs, long rsStride,
       const float* __restrict__ bias)
{
    constexpr int NT = (BM/TM)*(BN/TN);
    __shared__ float As[BK][BM + 4];
    __shared__ float Bs[BK][BN + 4];

    int z = blockIdx.z, bb = z >> 3, hh = z & 7;
    A  += (long)bb * sAb + (long)hh * sAh;
    Bp += (long)bb * sBb + (long)hh * sBh;
    C  += (long)bb * sCb + (long)hh * sCh;
    if (EPI == 3) rs += (long)z * rsStride;

    int m0 = blockIdx.y * BM, n0 = blockIdx.x * BN;
    int tid = threadIdx.x;
    int tx = tid % (BN / TN), ty = tid / (BN / TN);

    float acc[TM][TN];
    #pragma unroll
    for (int i = 0; i < TM; i++)
        #pragma unroll
        for (int j = 0; j < TN; j++) acc[i][j] = 0.0f;

    for (int k0 = 0; k0 < K; k0 += BK) {
        if (!TA) {
            #pragma unroll
            for (int idx = tid; idx < BM * BK; idx += NT) {
                int m = idx / BK, k = idx % BK;
                As[k][m] = A[(long)(m0 + m) * lda + (k0 + k)];
            }
        } else {
            #pragma unroll
            for (int idx = tid; idx < BM * BK; idx += NT) {
                int m = idx % BM, k = idx / BM;
                As[k][m] = A[(long)(k0 + k) * lda + (m0 + m)];
            }
        }
        if (!TB) {
            #pragma unroll
            for (int idx = tid; idx < BK * BN; idx += NT) {
                int n = idx % BN, k = idx / BN;
                Bs[k][n] = Bp[(long)(k0 + k) * ldb + (n0 + n)];
            }
        } else {
            #pragma unroll
            for (int idx = tid; idx < BK * BN; idx += NT) {
                int k = idx % BK, n = idx / BK;
                Bs[k][n] = Bp[(long)(n0 + n) * ldb + (k0 + k)];
            }
        }
        __syncthreads();

        #pragma unroll
        for (int k = 0; k < BK; k++) {
            float af[TM], bf[TN];
            #pragma unroll
            for (int i = 0; i < TM; i++) af[i] = As[k][ty * TM + i];
            #pragma unroll
            for (int j = 0; j < TN; j++) bf[j] = Bs[k][tx * TN + j];
            #pragma unroll
            for (int i = 0; i < TM; i++)
                #pragma unroll
                for (int j = 0; j < TN; j++)
                    acc[i][j] = fmaf(af[i], bf[j], acc[i][j]);
        }
        __syncthreads();
    }

    #pragma unroll
    for (int i = 0; i < TM; i++) {
        int row = m0 + ty * TM + i;
        float rsv = (EPI == 3) ? rs[row] : 1.0f;
        #pragma unroll
        for (int j = 0; j < TN; j++) {
            int col = n0 + tx * TN + j;
            float vv = acc[i][j];
            if      (EPI == 0) vv *= alpha;
            else if (EPI == 2) vv += bias[col];
            else if (EPI == 3) vv /= rsv;
            C[(long)row * ldc + col] = vv;
        }
    }
}

// ---------------- launch ----------------------------------------------------
extern "C" void kernel_launch(void* const* d_in, const int* in_sizes, int n_in,
                              void* d_out, int out_size) {
    (void)in_sizes; (void)n_in; (void)out_size;
    const float* x    = (const float*)d_in[0];
    const float* ctx  = (const float*)d_in[1];
    const float* gx   = (const float*)d_in[2];
    const float* bx   = (const float*)d_in[3];
    const float* gc   = (const float*)d_in[4];
    const float* bc   = (const float*)d_in[5];
    const float* Wqk  = (const float*)d_in[6];
    const float* Wcqk = (const float*)d_in[7];
    const float* Wv   = (const float*)d_in[8];
    const float* Wcv  = (const float*)d_in[9];
    const float* Wout = (const float*)d_in[10];
    const float* bout = (const float*)d_in[11];
    const float* Wco  = (const float*)d_in[12];
    const float* bco  = (const float*)d_in[13];
    float* out = (float*)d_out;

    float *p_xn, *p_cn, *p_qk, *p_cqk, *p_v, *p_cv, *p_vt, *p_sim;
    float *p_rsum, *p_texp, *p_csum, *p_outh, *p_ctxh;
    cudaGetSymbolAddress((void**)&p_xn,   g_xn);
    cudaGetSymbolAddress((void**)&p_cn,   g_cn);
    cudaGetSymbolAddress((void**)&p_qk,   g_qk);
    cudaGetSymbolAddress((void**)&p_cqk,  g_cqk);
    cudaGetSymbolAddress((void**)&p_v,    g_v);
    cudaGetSymbolAddress((void**)&p_cv,   g_cv);
    cudaGetSymbolAddress((void**)&p_vt,   g_vt);
    cudaGetSymbolAddress((void**)&p_sim,  g_sim);
    cudaGetSymbolAddress((void**)&p_rsum, g_rsum);
    cudaGetSymbolAddress((void**)&p_texp, g_texp);
    cudaGetSymbolAddress((void**)&p_csum, g_csum);
    cudaGetSymbolAddress((void**)&p_outh, g_outh);
    cudaGetSymbolAddress((void**)&p_ctxh, g_ctxh);

    // 1. layernorms
    ln_kernel<<<MROWS, 128>>>(x,   gx, bx, p_xn);
    ln_kernel<<<MROWS, 128>>>(ctx, gc, bc, p_cn);

    // 2. projections: [4096,512] @ [512,512]
    dim3 gproj(D_ / 64, MROWS / 128, 1);
    gemm_k<128,64,16,8,4,false,false,0><<<gproj,256>>>(p_xn,D_,0,0, Wqk, D_,0,0, p_qk, D_,0,0, D_, 1.0f, nullptr,0, nullptr);
    gemm_k<128,64,16,8,4,false,false,0><<<gproj,256>>>(p_cn,D_,0,0, Wcqk,D_,0,0, p_cqk,D_,0,0, D_, 1.0f, nullptr,0, nullptr);
    gemm_k<128,64,16,8,4,false,false,0><<<gproj,256>>>(p_xn,D_,0,0, Wv,  D_,0,0, p_v,  D_,0,0, D_, 1.0f, nullptr,0, nullptr);
    gemm_k<128,64,16,8,4,false,false,0><<<gproj,256>>>(p_cn,D_,0,0, Wcv, D_,0,0, p_cv, D_,0,0, D_, 1.0f, nullptr,0, nullptr);

    // 3. sim = SCALE * qk @ cqk^T  per (b,h):  [2048,64] x [2048,64]^T
    dim3 gsim(N_ / 64, N_ / 128, B_ * H_);
    gemm_k<128,64,16,8,4,false,true,0><<<gsim,256>>>(
        p_qk,  D_, NDL, DH_,
        p_cqk, D_, NDL, DH_,
        p_sim, N_, (long)H_ * NN, NN,
        DH_, 0.125f, nullptr, 0, nullptr);

    // 4. row softmax -> E in place, rsum, exp(rowmax)
    row_softmax_kernel<<<BHN, 256>>>(p_sim, p_rsum, p_texp);

    // 5. column sums of exp(sim) and scaled v
    zero_kernel<<<(BHN + 255) / 256, 256>>>(p_csum, BHN);
    colsum_kernel<<<dim3(N_ / 256, N_ / 256, B_ * H_), 256>>>(p_sim, p_texp, p_csum);
    scale_v_kernel<<<(B_ * N_ * D_ / 4) / 256, 256>>>((const float4*)p_v, p_texp, (float4*)p_vt);

    // 6. out_h = (E @ cv) / rsum   per (b,h):  [2048,2048] x [2048,64]
    dim3 gattn(1, N_ / 128, B_ * H_);
    gemm_k<128,64,16,8,4,false,false,3><<<gattn,256>>>(
        p_sim, N_, (long)H_ * NN, NN,
        p_cv,  D_, NDL, DH_,
        p_outh,D_, NDL, DH_,
        N_, 1.0f, p_rsum, N_, nullptr);

    // 7. ctx_h = (E^T @ vt) / csum  per (b,h):  A stored [i,j], used transposed
    gemm_k<128,64,16,8,4,true,false,3><<<gattn,256>>>(
        p_sim, N_, (long)H_ * NN, NN,
        p_vt,  D_, NDL, DH_,
        p_ctxh,D_, NDL, DH_,
        N_, 1.0f, p_csum, N_, nullptr);

    // 8. final projections (+bias) straight into d_out: [out, context_out]
    gemm_k<128,64,16,8,4,false,false,2><<<gproj,256>>>(p_outh,D_,0,0, Wout,D_,0,0, out,                 D_,0,0, D_, 1.0f, nullptr,0, bout);
    gemm_k<128,64,16,8,4,false,false,2><<<gproj,256>>>(p_ctxh,D_,0,0, Wco, D_,0,0, out + (long)B_*N_*D_,D_,0,0, D_, 1.0f, nullptr,0, bco);
}